// round 8
// baseline (speedup 1.0000x reference)
#include <cuda_runtime.h>
#include <cuda_bf16.h>

// actions: [B=4096, T=256, A=64] fp32
// out[b,0,a] = x[b,0,a]
// out[b,t,a] = out[b,t-1,a] + clip(x[b,t,a] - x[b,t-1,a], -0.5, 0.5)
//
// Persistent decoupled segmented scan.
//   grid = 296 CTAs (2/SM) x 512 threads; each CTA strides over ~14 batch rows.
//   Thread = (chunk c in 0..31, float4 lane a4 in 0..15); chunk = 8 timesteps.
//   Per row: dep-free load burst -> local reg scan -> warp-shuffle cross-chunk
//   scan (16 warps in parallel, one per lane) -> streaming store. Stores of
//   row r overlap loads of row r+1 (no barrier between them); no wave gaps.

#define TT     256
#define ROW4   16            // float4 lanes per (b,t) row
#define CHUNK  8             // timesteps per thread
#define NCHUNK (TT / CHUNK)  // 32
#define NB     4096
#define GRID   296           // 148 SMs * 2 CTAs
#define MAXD   0.5f

__device__ __forceinline__ float4 clip4(const float4 a, const float4 b)
{
    float4 d;
    d.x = fminf(fmaxf(a.x - b.x, -MAXD), MAXD);
    d.y = fminf(fmaxf(a.y - b.y, -MAXD), MAXD);
    d.z = fminf(fmaxf(a.z - b.z, -MAXD), MAXD);
    d.w = fminf(fmaxf(a.w - b.w, -MAXD), MAXD);
    return d;
}

__device__ __forceinline__ float4 add4(const float4 a, const float4 b)
{
    return make_float4(a.x + b.x, a.y + b.y, a.z + b.z, a.w + b.w);
}

__device__ __forceinline__ float4 shfl_up4(const float4 v, int off)
{
    float4 r;
    r.x = __shfl_up_sync(0xffffffffu, v.x, off);
    r.y = __shfl_up_sync(0xffffffffu, v.y, off);
    r.z = __shfl_up_sync(0xffffffffu, v.z, off);
    r.w = __shfl_up_sync(0xffffffffu, v.w, off);
    return r;
}

__global__ __launch_bounds__(512, 2) void smooth_scan_kernel(
    const float4* __restrict__ in, float4* __restrict__ out)
{
    __shared__ float4 s_last[NCHUNK][ROW4 + 1];  // +1 pad: break stride-256B banks
    __shared__ float4 s_pref[NCHUNK][ROW4 + 1];

    const unsigned tid = threadIdx.x;
    const unsigned a4  = tid & 15;   // float4 lane within row
    const unsigned c   = tid >> 4;   // time chunk (0..31)
    const unsigned w   = tid >> 5;   // warp id (0..15)
    const unsigned lid = tid & 31;   // lane in warp

    for (unsigned b = blockIdx.x; b < NB; b += GRID) {
        const size_t base = (size_t)b * (TT * ROW4) + (size_t)c * (CHUNK * ROW4) + a4;

        // ---- Phase 1: dependency-free streaming load ----
        float4 x[CHUNK];
        #pragma unroll
        for (int i = 0; i < CHUNK; ++i)
            x[i] = in[base + (size_t)i * ROW4];

        s_last[c][a4] = x[CHUNK - 1];
        __syncthreads();

        // ---- Phase 2a: in-place local scan ----
        // chunk 0: v[0] = x[0] (carries the base term); chunk c>0: v[0] =
        // clipped diff vs previous chunk's last raw x.
        {
            float4 raw_prev = x[0];
            if (c != 0) {
                float4 xp = s_last[c - 1][a4];
                x[0] = clip4(raw_prev, xp);
            }
            #pragma unroll
            for (int i = 1; i < CHUNK; ++i) {
                float4 cur = x[i];
                x[i] = add4(x[i - 1], clip4(cur, raw_prev));
                raw_prev = cur;
            }
        }

        // ---- Phase 2b: exclusive scan of chunk sums, one warp per lane ----
        s_pref[c][a4] = x[CHUNK - 1];
        __syncthreads();

        {
            // warp w owns lane a4 = w; lane lid holds chunk lid's sum
            float4 v = s_pref[lid][w];
            #pragma unroll
            for (int off = 1; off < 32; off <<= 1) {
                float4 n = shfl_up4(v, off);
                if ((int)lid >= off) v = add4(v, n);
            }
            float4 e = shfl_up4(v, 1);                 // exclusive
            if (lid == 0) e = make_float4(0.f, 0.f, 0.f, 0.f);
            s_pref[lid][w] = e;
        }
        __syncthreads();

        const float4 P = s_pref[c][a4];

        // ---- Phase 3: streaming store (overlaps next row's loads) ----
        #pragma unroll
        for (int i = 0; i < CHUNK; ++i)
            out[base + (size_t)i * ROW4] = add4(x[i], P);

        __syncthreads();   // protect s_last/s_pref before next row's writes
    }
}

extern "C" void kernel_launch(void* const* d_in, const int* in_sizes, int n_in,
                              void* d_out, int out_size)
{
    const float4* in  = (const float4*)d_in[0];
    float4*       out = (float4*)d_out;

    smooth_scan_kernel<<<GRID, NCHUNK * ROW4>>>(in, out);  // 296 x 512
}

// round 9
// speedup vs baseline: 1.1481x; 1.1481x over previous
#include <cuda_runtime.h>
#include <cuda_bf16.h>

// actions: [B=4096, T=256, A=64] fp32
// out[b,0,a] = x[b,0,a]
// out[b,t,a] = out[b,t-1,a] + clip(x[b,t,a] - x[b,t-1,a], -0.5, 0.5)
//
// Decoupled segmented scan (R6 winner) + parallel phase-2b.
// CTA per batch row (4096 CTAs x 256 threads). Thread = (chunk c 0..15,
// float4 lane a4 0..15); chunk = 16 timesteps.
//  Phase 1:  dependency-free load of 16 float4 per thread (true MLP=16).
//  Phase 2a: in-register local scan.
//  Phase 2b: cross-chunk exclusive scan done by ALL 8 warps in parallel —
//            each half-warp shuffle-scans the 16 chunk sums of one a4 lane
//            (R6 used 16 threads x 16 serial smem iterations: ~600-cyc bubble).
//  Phase 3:  pure streaming store of 16 float4.

#define TT     256
#define ROW4   16            // float4 lanes per (b,t) row
#define CHUNK  16            // timesteps per thread
#define NCHUNK (TT / CHUNK)  // 16
#define MAXD   0.5f

__device__ __forceinline__ float4 clip4(const float4 a, const float4 b)
{
    float4 d;
    d.x = fminf(fmaxf(a.x - b.x, -MAXD), MAXD);
    d.y = fminf(fmaxf(a.y - b.y, -MAXD), MAXD);
    d.z = fminf(fmaxf(a.z - b.z, -MAXD), MAXD);
    d.w = fminf(fmaxf(a.w - b.w, -MAXD), MAXD);
    return d;
}

__device__ __forceinline__ float4 add4(const float4 a, const float4 b)
{
    return make_float4(a.x + b.x, a.y + b.y, a.z + b.z, a.w + b.w);
}

__device__ __forceinline__ float4 shfl_up4(const float4 v, int off)
{
    float4 r;
    r.x = __shfl_up_sync(0xffffffffu, v.x, off);
    r.y = __shfl_up_sync(0xffffffffu, v.y, off);
    r.z = __shfl_up_sync(0xffffffffu, v.z, off);
    r.w = __shfl_up_sync(0xffffffffu, v.w, off);
    return r;
}

__global__ __launch_bounds__(256, 2) void smooth_scan_kernel(
    const float4* __restrict__ in, float4* __restrict__ out)
{
    __shared__ float4 s_last[NCHUNK][ROW4 + 1];  // +1 pad: kill 16-way conflicts
    __shared__ float4 s_pref[NCHUNK][ROW4 + 1];  //   on transposed accesses

    const unsigned b   = blockIdx.x;
    const unsigned tid = threadIdx.x;
    const unsigned a4  = tid & 15;   // float4 lane within row
    const unsigned c   = tid >> 4;   // time chunk (0..15)
    const unsigned w   = tid >> 5;   // warp id (0..7)
    const unsigned lid = tid & 31;   // lane in warp

    const size_t base = (size_t)b * (TT * ROW4) + (size_t)c * (CHUNK * ROW4) + a4;

    // ---- Phase 1: dependency-free streaming load ----
    float4 x[CHUNK];
    #pragma unroll
    for (int i = 0; i < CHUNK; ++i)
        x[i] = in[base + (size_t)i * ROW4];

    s_last[c][a4] = x[CHUNK - 1];
    __syncthreads();

    // ---- Phase 2a: in-place local scan ----
    // chunk 0: v[0] = x[0] (carries the base term); chunk c>0: v[0] = clipped
    // diff vs previous chunk's last raw x. v[i] = v[i-1] + clip(x[i]-x[i-1]).
    {
        float4 raw_prev = x[0];
        if (c != 0) {
            float4 xp = s_last[c - 1][a4];
            x[0] = clip4(raw_prev, xp);
        }
        #pragma unroll
        for (int i = 1; i < CHUNK; ++i) {
            float4 cur = x[i];
            x[i] = add4(x[i - 1], clip4(cur, raw_prev));
            raw_prev = cur;
        }
    }

    // ---- Phase 2b: exclusive scan of chunk sums, all warps in parallel ----
    s_pref[c][a4] = x[CHUNK - 1];
    __syncthreads();

    {
        // Warp w owns lanes a = 2w + seg; each 16-lane half-warp scans the
        // 16 chunk sums of one a4 lane.
        const unsigned pos = lid & 15;     // chunk index within segment
        const unsigned seg = lid >> 4;     // which of the warp's two lanes
        const unsigned a   = 2 * w + seg;

        float4 v = s_pref[pos][a];
        #pragma unroll
        for (int off = 1; off < 16; off <<= 1) {
            float4 n = shfl_up4(v, off);
            if ((int)pos >= off) v = add4(v, n);   // segment-local guard
        }
        float4 e = shfl_up4(v, 1);                 // exclusive shift
        if (pos == 0) e = make_float4(0.f, 0.f, 0.f, 0.f);
        s_pref[pos][a] = e;
    }
    __syncthreads();

    const float4 P = s_pref[c][a4];

    // ---- Phase 3: streaming store ----
    #pragma unroll
    for (int i = 0; i < CHUNK; ++i)
        out[base + (size_t)i * ROW4] = add4(x[i], P);
}

extern "C" void kernel_launch(void* const* d_in, const int* in_sizes, int n_in,
                              void* d_out, int out_size)
{
    const float4* in  = (const float4*)d_in[0];
    float4*       out = (float4*)d_out;

    smooth_scan_kernel<<<4096, NCHUNK * ROW4>>>(in, out);  // 4096 x 256
}

// round 10
// speedup vs baseline: 1.1657x; 1.0153x over previous
#include <cuda_runtime.h>
#include <cuda_bf16.h>

// actions: [B=4096, T=256, A=64] fp32
// out[b,0,a] = x[b,0,a]
// out[b,t,a] = out[b,t-1,a] + clip(x[b,t,a] - x[b,t-1,a], -0.5, 0.5)
//
// Decoupled segmented scan, half-row CTAs: the A dimension is independent, so
// each batch row is split across 2 CTAs (8 float4 lanes each). 8192 CTAs x
// 256 threads, CHUNK=8 -> ~50 regs -> 4 CTAs/SM: four INDEPENDENT phase
// clocks per SM (R6/R7/R9 had two lockstep clocks -> DRAM idle whenever both
// were in a compute phase).
//  Phase 1:  dep-free load of 8 float4/thread (warp = 4 full 128B lines/LDG).
//  Phase 2a: in-register local scan.
//  Phase 2b: warp w shuffle-scans the 32 chunk sums of lane w (8 warps, all
//            parallel, no serial smem walk).
//  Phase 3:  streaming store.

#define TT     256
#define ROW4   16            // float4 lanes per full (b,t) row
#define LANES  8             // float4 lanes owned by this CTA
#define CHUNK  8             // timesteps per thread
#define NCHUNK (TT / CHUNK)  // 32
#define MAXD   0.5f

__device__ __forceinline__ float4 clip4(const float4 a, const float4 b)
{
    float4 d;
    d.x = fminf(fmaxf(a.x - b.x, -MAXD), MAXD);
    d.y = fminf(fmaxf(a.y - b.y, -MAXD), MAXD);
    d.z = fminf(fmaxf(a.z - b.z, -MAXD), MAXD);
    d.w = fminf(fmaxf(a.w - b.w, -MAXD), MAXD);
    return d;
}

__device__ __forceinline__ float4 add4(const float4 a, const float4 b)
{
    return make_float4(a.x + b.x, a.y + b.y, a.z + b.z, a.w + b.w);
}

__device__ __forceinline__ float4 shfl_up4(const float4 v, int off)
{
    float4 r;
    r.x = __shfl_up_sync(0xffffffffu, v.x, off);
    r.y = __shfl_up_sync(0xffffffffu, v.y, off);
    r.z = __shfl_up_sync(0xffffffffu, v.z, off);
    r.w = __shfl_up_sync(0xffffffffu, v.w, off);
    return r;
}

__global__ __launch_bounds__(256, 4) void smooth_scan_kernel(
    const float4* __restrict__ in, float4* __restrict__ out)
{
    __shared__ float4 s_last[NCHUNK][LANES + 1];  // raw x at chunk's last t
    __shared__ float4 s_pref[NCHUNK][LANES + 1];  // chunk sums -> excl prefixes

    const unsigned blk  = blockIdx.x;
    const unsigned b    = blk >> 1;          // batch row
    const unsigned half = blk & 1;           // which 8-lane half of the row
    const unsigned tid  = threadIdx.x;
    const unsigned a4   = tid & 7;           // lane within half-row (0..7)
    const unsigned c    = tid >> 3;          // time chunk (0..31)
    const unsigned w    = tid >> 5;          // warp id (0..7)
    const unsigned lid  = tid & 31;          // lane in warp

    const size_t base = (size_t)b * (TT * ROW4)
                      + (size_t)c * (CHUNK * ROW4)
                      + half * LANES + a4;

    // ---- Phase 1: dependency-free streaming load ----
    float4 x[CHUNK];
    #pragma unroll
    for (int i = 0; i < CHUNK; ++i)
        x[i] = in[base + (size_t)i * ROW4];

    s_last[c][a4] = x[CHUNK - 1];
    __syncthreads();

    // ---- Phase 2a: in-place local scan ----
    // chunk 0: v[0] = x[0] (carries the base term); chunk c>0: v[0] = clipped
    // diff vs previous chunk's last raw x. v[i] = v[i-1] + clip(x[i]-x[i-1]).
    {
        float4 raw_prev = x[0];
        if (c != 0) {
            float4 xp = s_last[c - 1][a4];
            x[0] = clip4(raw_prev, xp);
        }
        #pragma unroll
        for (int i = 1; i < CHUNK; ++i) {
            float4 cur = x[i];
            x[i] = add4(x[i - 1], clip4(cur, raw_prev));
            raw_prev = cur;
        }
    }

    // ---- Phase 2b: exclusive scan of 32 chunk sums, warp w -> lane w ----
    s_pref[c][a4] = x[CHUNK - 1];
    __syncthreads();

    {
        float4 v = s_pref[lid][w];          // lane lid holds chunk lid's sum
        #pragma unroll
        for (int off = 1; off < 32; off <<= 1) {
            float4 n = shfl_up4(v, off);
            if ((int)lid >= off) v = add4(v, n);
        }
        float4 e = shfl_up4(v, 1);          // exclusive shift
        if (lid == 0) e = make_float4(0.f, 0.f, 0.f, 0.f);
        s_pref[lid][w] = e;
    }
    __syncthreads();

    const float4 P = s_pref[c][a4];

    // ---- Phase 3: streaming store ----
    #pragma unroll
    for (int i = 0; i < CHUNK; ++i)
        out[base + (size_t)i * ROW4] = add4(x[i], P);
}

extern "C" void kernel_launch(void* const* d_in, const int* in_sizes, int n_in,
                              void* d_out, int out_size)
{
    const float4* in  = (const float4*)d_in[0];
    float4*       out = (float4*)d_out;

    smooth_scan_kernel<<<4096 * 2, 256>>>(in, out);  // 8192 x 256
}